// round 1
// baseline (speedup 1.0000x reference)
#include <cuda_runtime.h>
#include <cuda_bf16.h>

// Segment-wise mean(|diff|): x flattened is [num_segs, L] contiguous.
// out[g] = mean_{i=0..L-2} |x[g*L + i + 1] - x[g*L + i]|
//
// One CTA per segment. float4 vectorized loads (3 gaps intra-vector),
// one scalar neighbor load per vector for the cross-vector gap (L1 hit).

__global__ __launch_bounds__(256) void seg_meandiff_kernel(
    const float* __restrict__ x,
    float* __restrict__ out,
    int L)
{
    const long long seg = blockIdx.x;
    const float* __restrict__ p = x + seg * (long long)L;
    const int tid = threadIdx.x;

    float sum = 0.0f;

    if ((L & 3) == 0) {
        // Vector path: L divisible by 4.
        const float4* __restrict__ p4 = reinterpret_cast<const float4*>(p);
        const int n4 = L >> 2;
        for (int i = tid; i < n4; i += blockDim.x) {
            float4 v = __ldg(p4 + i);
            sum += fabsf(v.y - v.x) + fabsf(v.z - v.y) + fabsf(v.w - v.z);
            int nxt_idx = 4 * i + 4;
            if (nxt_idx < L) {
                float nxt = __ldg(p + nxt_idx);   // L1/L2 hit (neighbor's line)
                sum += fabsf(nxt - v.w);
            }
        }
    } else {
        // Scalar fallback (not expected for this shape).
        for (int i = tid; i < L - 1; i += blockDim.x) {
            sum += fabsf(__ldg(p + i + 1) - __ldg(p + i));
        }
    }

    // Warp reduction
    #pragma unroll
    for (int off = 16; off > 0; off >>= 1)
        sum += __shfl_down_sync(0xFFFFFFFFu, sum, off);

    // Block reduction across warps
    __shared__ float wsum[8];  // up to 256 threads = 8 warps
    const int lane = tid & 31;
    const int wid  = tid >> 5;
    if (lane == 0) wsum[wid] = sum;
    __syncthreads();

    if (wid == 0) {
        const int nwarps = blockDim.x >> 5;
        float s = (lane < nwarps) ? wsum[lane] : 0.0f;
        #pragma unroll
        for (int off = 4; off > 0; off >>= 1)
            s += __shfl_down_sync(0xFFFFFFFFu, s, off);
        if (lane == 0)
            out[seg] = s / (float)(L - 1);
    }
}

extern "C" void kernel_launch(void* const* d_in, const int* in_sizes, int n_in,
                              void* d_out, int out_size)
{
    const float* x = (const float*)d_in[0];
    float* out = (float*)d_out;

    const long long total = (long long)in_sizes[0];
    const int num_segs = out_size;                 // B * target_len
    const int L = (int)(total / (long long)num_segs);  // segment length

    seg_meandiff_kernel<<<num_segs, 256>>>(x, out, L);
}

// round 2
// speedup vs baseline: 1.2474x; 1.2474x over previous
#include <cuda_runtime.h>
#include <cuda_bf16.h>

// Segment-wise mean(|diff|): x flattened is [num_segs, L] contiguous.
// out[g] = mean_{i=0..L-2} |x[g*L+i+1] - x[g*L+i]|
//
// One CTA (256 threads) per segment. float4 loads give 3 gaps free;
// the cross-vector gap comes from __shfl_down (next lane's v.x).
// Only lane 31 does a scalar load for the warp-boundary junction.
// Manual 2x unroll: both LDG.128 issued before any compute (MLP=2).

__global__ __launch_bounds__(256) void seg_meandiff_kernel(
    const float* __restrict__ x,
    float* __restrict__ out,
    int L, float inv)
{
    const long long seg = blockIdx.x;
    const float* __restrict__ p = x + seg * (long long)L;
    const int tid  = threadIdx.x;
    const int lane = tid & 31;

    float sum = 0.0f;

    if ((L & 3) == 0) {
        const float4* __restrict__ p4 = reinterpret_cast<const float4*>(p);
        const int n4 = L >> 2;

        // All threads iterate the same count so shuffles stay converged.
        for (int i0 = 0; i0 < n4; i0 += 512) {
            const int ia = i0 + tid;
            const int ib = i0 + tid + 256;
            const bool acta = (ia < n4);
            const bool actb = (ib < n4);

            // Issue both wide loads up front.
            float4 va = acta ? __ldg(p4 + ia) : make_float4(0.f, 0.f, 0.f, 0.f);
            float4 vb = actb ? __ldg(p4 + ib) : make_float4(0.f, 0.f, 0.f, 0.f);

            // Cross-vector gap value = next lane's v.x.
            float nxa = __shfl_down_sync(0xFFFFFFFFu, va.x, 1);
            float nxb = __shfl_down_sync(0xFFFFFFFFu, vb.x, 1);

            if (lane == 31) {
                const int na = 4 * ia + 4;
                const int nb = 4 * ib + 4;
                nxa = (na < L) ? __ldg(p + na) : va.w;  // zero contribution if OOB
                nxb = (nb < L) ? __ldg(p + nb) : vb.w;
            } else {
                // If neighbor vector is past the end, gap doesn't exist.
                if (4 * ia + 4 >= L) nxa = va.w;
                if (4 * ib + 4 >= L) nxb = vb.w;
            }

            if (acta)
                sum += fabsf(va.y - va.x) + fabsf(va.z - va.y)
                     + fabsf(va.w - va.z) + fabsf(nxa - va.w);
            if (actb)
                sum += fabsf(vb.y - vb.x) + fabsf(vb.z - vb.y)
                     + fabsf(vb.w - vb.z) + fabsf(nxb - vb.w);
        }
    } else {
        // Scalar fallback (not hit for this shape).
        for (int i = tid; i < L - 1; i += blockDim.x)
            sum += fabsf(__ldg(p + i + 1) - __ldg(p + i));
    }

    // Warp reduction
    #pragma unroll
    for (int off = 16; off > 0; off >>= 1)
        sum += __shfl_down_sync(0xFFFFFFFFu, sum, off);

    // Block reduction across 8 warps
    __shared__ float wsum[8];
    const int wid = tid >> 5;
    if (lane == 0) wsum[wid] = sum;
    __syncthreads();

    if (wid == 0) {
        float s = (lane < 8) ? wsum[lane] : 0.0f;
        #pragma unroll
        for (int off = 4; off > 0; off >>= 1)
            s += __shfl_down_sync(0xFFFFFFFFu, s, off);
        if (lane == 0)
            out[seg] = s * inv;
    }
}

extern "C" void kernel_launch(void* const* d_in, const int* in_sizes, int n_in,
                              void* d_out, int out_size)
{
    const float* x = (const float*)d_in[0];
    float* out = (float*)d_out;

    const long long total = (long long)in_sizes[0];
    const int num_segs = out_size;                     // B * target_len
    const int L = (int)(total / (long long)num_segs);  // segment length
    const float inv = 1.0f / (float)(L - 1);

    seg_meandiff_kernel<<<num_segs, 256>>>(x, out, L, inv);
}

// round 3
// speedup vs baseline: 1.2730x; 1.0206x over previous
#include <cuda_runtime.h>
#include <cuda_bf16.h>

// Segment-wise mean(|diff|): x flattened is [num_segs, L] contiguous.
// out[g] = mean_{i=0..L-2} |x[g*L+i+1] - x[g*L+i]|
//
// Fast path: ONE WARP per segment. The warp walks the segment in chunks of
// 32 float4 (512 B, perfectly coalesced). Cross-vector junctions come from a
// single rotating shuffle per chunk:
//   src = (lane==0) ? next_chunk.x : v.x;  nx = shfl(src, (lane+1)&31)
// lane l<31 gets lane l+1's v.x (same chunk); lane 31 gets next chunk's first
// element. No scalar loads, no divergence, no smem, no __syncthreads.

__global__ __launch_bounds__(256) void seg_warp_kernel(
    const float* __restrict__ x,
    float* __restrict__ out,
    int n4,        // float4s per segment (L/4), multiple of 32
    int nchunks,   // n4 / 32
    float inv,     // 1/(L-1)
    int num_segs)
{
    const int gwarp = (blockIdx.x * 256 + threadIdx.x) >> 5;
    const int lane  = threadIdx.x & 31;
    if (gwarp >= num_segs) return;

    const float4* __restrict__ p4 =
        reinterpret_cast<const float4*>(x) + (long long)gwarp * n4;

    float sum = 0.0f;
    float4 v = __ldg(p4 + lane);

    #pragma unroll 4
    for (int c = 1; c < nchunks; c++) {
        float4 nv = __ldg(p4 + c * 32 + lane);
        float src = (lane == 0) ? nv.x : v.x;
        float nx  = __shfl_sync(0xFFFFFFFFu, src, (lane + 1) & 31);
        sum += fabsf(v.y - v.x) + fabsf(v.z - v.y)
             + fabsf(v.w - v.z) + fabsf(nx  - v.w);
        v = nv;
    }

    // Last chunk: lane 31 has no successor (segment end) -> zero contribution.
    {
        float nx = __shfl_sync(0xFFFFFFFFu, v.x, (lane + 1) & 31);
        if (lane == 31) nx = v.w;
        sum += fabsf(v.y - v.x) + fabsf(v.z - v.y)
             + fabsf(v.w - v.z) + fabsf(nx  - v.w);
    }

    // Warp reduction, lane 0 writes the segment mean.
    #pragma unroll
    for (int off = 16; off > 0; off >>= 1)
        sum += __shfl_down_sync(0xFFFFFFFFu, sum, off);
    if (lane == 0)
        out[gwarp] = sum * inv;
}

// Generic fallback: one CTA per segment, scalar loads (any L >= 2).
__global__ __launch_bounds__(256) void seg_generic_kernel(
    const float* __restrict__ x,
    float* __restrict__ out,
    int L, float inv)
{
    const long long seg = blockIdx.x;
    const float* __restrict__ p = x + seg * (long long)L;
    const int tid = threadIdx.x;

    float sum = 0.0f;
    for (int i = tid; i < L - 1; i += blockDim.x)
        sum += fabsf(__ldg(p + i + 1) - __ldg(p + i));

    #pragma unroll
    for (int off = 16; off > 0; off >>= 1)
        sum += __shfl_down_sync(0xFFFFFFFFu, sum, off);

    __shared__ float wsum[8];
    const int lane = tid & 31, wid = tid >> 5;
    if (lane == 0) wsum[wid] = sum;
    __syncthreads();
    if (wid == 0) {
        float s = (lane < 8) ? wsum[lane] : 0.0f;
        #pragma unroll
        for (int off = 4; off > 0; off >>= 1)
            s += __shfl_down_sync(0xFFFFFFFFu, s, off);
        if (lane == 0) out[seg] = s * inv;
    }
}

extern "C" void kernel_launch(void* const* d_in, const int* in_sizes, int n_in,
                              void* d_out, int out_size)
{
    const float* x = (const float*)d_in[0];
    float* out = (float*)d_out;

    const long long total = (long long)in_sizes[0];
    const int num_segs = out_size;                     // B * target_len
    const int L = (int)(total / (long long)num_segs);  // segment length
    const float inv = 1.0f / (float)(L - 1);

    if ((L & 127) == 0) {
        // Warp-per-segment fast path (L multiple of 128 floats).
        const int n4 = L >> 2;
        const int nchunks = n4 >> 5;
        const int warps_needed = num_segs;
        const int ctas = (warps_needed * 32 + 255) / 256;
        seg_warp_kernel<<<ctas, 256>>>(x, out, n4, nchunks, inv, num_segs);
    } else {
        seg_generic_kernel<<<num_segs, 256>>>(x, out, L, inv);
    }
}

// round 4
// speedup vs baseline: 1.3765x; 1.0813x over previous
#include <cuda_runtime.h>
#include <cuda_bf16.h>

// Segment-wise mean(|diff|): x flattened is [num_segs, L] contiguous.
// out[g] = mean_{i=0..L-2} |x[g*L+i+1] - x[g*L+i]|
//
// Fast path: one warp per segment, explicit double-buffered pipeline.
// Each batch = 4 chunks of 32 float4 (2 KB). Loads of batch k+1 are issued
// BEFORE compute of batch k, keeping 4-8 LDG.128 in flight per warp at all
// times. Cross-vector junctions via one rotating shuffle per chunk.

#define BATCH 4

__global__ __launch_bounds__(256) void seg_warp_pipe_kernel(
    const float* __restrict__ x,
    float* __restrict__ out,
    int n4,         // float4s per segment (L/4), multiple of 128
    int nbatches,   // n4 / (32*BATCH), >= 2
    float inv,      // 1/(L-1)
    int num_segs)
{
    const int gwarp = (blockIdx.x * 256 + threadIdx.x) >> 5;
    const int lane  = threadIdx.x & 31;
    if (gwarp >= num_segs) return;

    const float4* __restrict__ p4 =
        reinterpret_cast<const float4*>(x) + (long long)gwarp * n4 + lane;

    float4 buf[BATCH];
    #pragma unroll
    for (int i = 0; i < BATCH; i++)
        buf[i] = __ldcs(p4 + i * 32);

    float sum = 0.0f;

    for (int b = 1; b < nbatches; b++) {
        // Issue next batch's loads first (independent of current compute).
        float4 nbuf[BATCH];
        const float4* q = p4 + b * (BATCH * 32);
        #pragma unroll
        for (int i = 0; i < BATCH; i++)
            nbuf[i] = __ldcs(q + i * 32);

        // Compute current batch.
        #pragma unroll
        for (int i = 0; i < BATCH; i++) {
            const float nextx = (i < BATCH - 1) ? buf[i + 1].x : nbuf[0].x;
            const float src = (lane == 0) ? nextx : buf[i].x;
            const float nx  = __shfl_sync(0xFFFFFFFFu, src, (lane + 1) & 31);
            sum += fabsf(buf[i].y - buf[i].x) + fabsf(buf[i].z - buf[i].y)
                 + fabsf(buf[i].w - buf[i].z) + fabsf(nx - buf[i].w);
        }

        #pragma unroll
        for (int i = 0; i < BATCH; i++) buf[i] = nbuf[i];
    }

    // Final batch: last chunk's lane 31 has no successor (segment end).
    #pragma unroll
    for (int i = 0; i < BATCH; i++) {
        const float nextx = (i < BATCH - 1) ? buf[i + 1].x : buf[i].x;
        const float src = (lane == 0) ? nextx : buf[i].x;
        float nx = __shfl_sync(0xFFFFFFFFu, src, (lane + 1) & 31);
        if (i == BATCH - 1 && lane == 31) nx = buf[i].w;  // zero contribution
        sum += fabsf(buf[i].y - buf[i].x) + fabsf(buf[i].z - buf[i].y)
             + fabsf(buf[i].w - buf[i].z) + fabsf(nx - buf[i].w);
    }

    // Warp reduction, lane 0 writes segment mean.
    #pragma unroll
    for (int off = 16; off > 0; off >>= 1)
        sum += __shfl_down_sync(0xFFFFFFFFu, sum, off);
    if (lane == 0)
        out[gwarp] = sum * inv;
}

// Mid path: warp per segment, simple loop (L multiple of 128 floats).
__global__ __launch_bounds__(256) void seg_warp_kernel(
    const float* __restrict__ x,
    float* __restrict__ out,
    int n4, int nchunks, float inv, int num_segs)
{
    const int gwarp = (blockIdx.x * 256 + threadIdx.x) >> 5;
    const int lane  = threadIdx.x & 31;
    if (gwarp >= num_segs) return;

    const float4* __restrict__ p4 =
        reinterpret_cast<const float4*>(x) + (long long)gwarp * n4;

    float sum = 0.0f;
    float4 v = __ldg(p4 + lane);

    #pragma unroll 4
    for (int c = 1; c < nchunks; c++) {
        float4 nv = __ldg(p4 + c * 32 + lane);
        float src = (lane == 0) ? nv.x : v.x;
        float nx  = __shfl_sync(0xFFFFFFFFu, src, (lane + 1) & 31);
        sum += fabsf(v.y - v.x) + fabsf(v.z - v.y)
             + fabsf(v.w - v.z) + fabsf(nx  - v.w);
        v = nv;
    }
    {
        float nx = __shfl_sync(0xFFFFFFFFu, v.x, (lane + 1) & 31);
        if (lane == 31) nx = v.w;
        sum += fabsf(v.y - v.x) + fabsf(v.z - v.y)
             + fabsf(v.w - v.z) + fabsf(nx  - v.w);
    }

    #pragma unroll
    for (int off = 16; off > 0; off >>= 1)
        sum += __shfl_down_sync(0xFFFFFFFFu, sum, off);
    if (lane == 0)
        out[gwarp] = sum * inv;
}

// Generic fallback: one CTA per segment, scalar loads (any L >= 2).
__global__ __launch_bounds__(256) void seg_generic_kernel(
    const float* __restrict__ x,
    float* __restrict__ out,
    int L, float inv)
{
    const long long seg = blockIdx.x;
    const float* __restrict__ p = x + seg * (long long)L;
    const int tid = threadIdx.x;

    float sum = 0.0f;
    for (int i = tid; i < L - 1; i += blockDim.x)
        sum += fabsf(__ldg(p + i + 1) - __ldg(p + i));

    #pragma unroll
    for (int off = 16; off > 0; off >>= 1)
        sum += __shfl_down_sync(0xFFFFFFFFu, sum, off);

    __shared__ float wsum[8];
    const int lane = tid & 31, wid = tid >> 5;
    if (lane == 0) wsum[wid] = sum;
    __syncthreads();
    if (wid == 0) {
        float s = (lane < 8) ? wsum[lane] : 0.0f;
        #pragma unroll
        for (int off = 4; off > 0; off >>= 1)
            s += __shfl_down_sync(0xFFFFFFFFu, s, off);
        if (lane == 0) out[seg] = s * inv;
    }
}

extern "C" void kernel_launch(void* const* d_in, const int* in_sizes, int n_in,
                              void* d_out, int out_size)
{
    const float* x = (const float*)d_in[0];
    float* out = (float*)d_out;

    const long long total = (long long)in_sizes[0];
    const int num_segs = out_size;                     // B * target_len
    const int L = (int)(total / (long long)num_segs);  // segment length
    const float inv = 1.0f / (float)(L - 1);

    const int ctas = (num_segs * 32 + 255) / 256;

    if ((L % (BATCH * 128)) == 0 && L / (BATCH * 128) >= 2) {
        const int n4 = L >> 2;
        const int nbatches = n4 / (BATCH * 32);
        seg_warp_pipe_kernel<<<ctas, 256>>>(x, out, n4, nbatches, inv, num_segs);
    } else if ((L & 127) == 0) {
        const int n4 = L >> 2;
        seg_warp_kernel<<<ctas, 256>>>(x, out, n4, n4 >> 5, inv, num_segs);
    } else {
        seg_generic_kernel<<<num_segs, 256>>>(x, out, L, inv);
    }
}

// round 5
// speedup vs baseline: 1.5277x; 1.1098x over previous
#include <cuda_runtime.h>
#include <cuda_bf16.h>

// Segment-wise mean(|diff|): x flattened is [num_segs, L] contiguous.
// out[g] = mean_{i=0..L-2} |x[g*L+i+1] - x[g*L+i]|
//
// Fast path: one warp per segment, double-buffered load pipeline (BATCH=4
// chunks of 32 float4 = 2 KB per batch) + an L2 prefetch prologue that pulls
// the segment's remaining lines into L2 register-free, so demand loads for
// batches 1..N see L2-hit latency. Cross-vector junctions via one rotating
// shuffle per chunk. No smem, no __syncthreads.

#define BATCH 4

__global__ __launch_bounds__(256) void seg_warp_pipe_kernel(
    const float* __restrict__ x,
    float* __restrict__ out,
    int n4,         // float4s per segment (L/4), multiple of 128
    int nbatches,   // n4 / (32*BATCH), >= 2
    float inv,      // 1/(L-1)
    int num_segs)
{
    const int gwarp = (blockIdx.x * 256 + threadIdx.x) >> 5;
    const int lane  = threadIdx.x & 31;
    if (gwarp >= num_segs) return;

    const float4* __restrict__ pseg =
        reinterpret_cast<const float4*>(x) + (long long)gwarp * n4;
    const float4* __restrict__ p4 = pseg + lane;

    // L2 prefetch prologue: pull lines for batches 1..nbatches-1 into L2.
    // Segment has n4/8 128-byte lines; batch 0 (first 16 lines) is demand-
    // loaded immediately below, so start at line 16. Register-free MLP.
    {
        const char* base = reinterpret_cast<const char*>(pseg);
        const int nlines = n4 >> 3;
        for (int ln = 16 + lane; ln < nlines; ln += 32) {
            asm volatile("prefetch.global.L2 [%0];" :: "l"(base + (long long)ln * 128));
        }
    }

    float4 buf[BATCH];
    #pragma unroll
    for (int i = 0; i < BATCH; i++)
        buf[i] = __ldcs(p4 + i * 32);

    float sum = 0.0f;

    for (int b = 1; b < nbatches; b++) {
        // Issue next batch's loads first (independent of current compute).
        float4 nbuf[BATCH];
        const float4* q = p4 + b * (BATCH * 32);
        #pragma unroll
        for (int i = 0; i < BATCH; i++)
            nbuf[i] = __ldcs(q + i * 32);

        // Compute current batch.
        #pragma unroll
        for (int i = 0; i < BATCH; i++) {
            const float nextx = (i < BATCH - 1) ? buf[i + 1].x : nbuf[0].x;
            const float src = (lane == 0) ? nextx : buf[i].x;
            const float nx  = __shfl_sync(0xFFFFFFFFu, src, (lane + 1) & 31);
            sum += fabsf(buf[i].y - buf[i].x) + fabsf(buf[i].z - buf[i].y)
                 + fabsf(buf[i].w - buf[i].z) + fabsf(nx - buf[i].w);
        }

        #pragma unroll
        for (int i = 0; i < BATCH; i++) buf[i] = nbuf[i];
    }

    // Final batch: last chunk's lane 31 has no successor (segment end).
    #pragma unroll
    for (int i = 0; i < BATCH; i++) {
        const float nextx = (i < BATCH - 1) ? buf[i + 1].x : buf[i].x;
        const float src = (lane == 0) ? nextx : buf[i].x;
        float nx = __shfl_sync(0xFFFFFFFFu, src, (lane + 1) & 31);
        if (i == BATCH - 1 && lane == 31) nx = buf[i].w;  // zero contribution
        sum += fabsf(buf[i].y - buf[i].x) + fabsf(buf[i].z - buf[i].y)
             + fabsf(buf[i].w - buf[i].z) + fabsf(nx - buf[i].w);
    }

    // Warp reduction, lane 0 writes segment mean.
    #pragma unroll
    for (int off = 16; off > 0; off >>= 1)
        sum += __shfl_down_sync(0xFFFFFFFFu, sum, off);
    if (lane == 0)
        out[gwarp] = sum * inv;
}

// Mid path: warp per segment, simple loop (L multiple of 128 floats).
__global__ __launch_bounds__(256) void seg_warp_kernel(
    const float* __restrict__ x,
    float* __restrict__ out,
    int n4, int nchunks, float inv, int num_segs)
{
    const int gwarp = (blockIdx.x * 256 + threadIdx.x) >> 5;
    const int lane  = threadIdx.x & 31;
    if (gwarp >= num_segs) return;

    const float4* __restrict__ p4 =
        reinterpret_cast<const float4*>(x) + (long long)gwarp * n4;

    float sum = 0.0f;
    float4 v = __ldg(p4 + lane);

    #pragma unroll 4
    for (int c = 1; c < nchunks; c++) {
        float4 nv = __ldg(p4 + c * 32 + lane);
        float src = (lane == 0) ? nv.x : v.x;
        float nx  = __shfl_sync(0xFFFFFFFFu, src, (lane + 1) & 31);
        sum += fabsf(v.y - v.x) + fabsf(v.z - v.y)
             + fabsf(v.w - v.z) + fabsf(nx  - v.w);
        v = nv;
    }
    {
        float nx = __shfl_sync(0xFFFFFFFFu, v.x, (lane + 1) & 31);
        if (lane == 31) nx = v.w;
        sum += fabsf(v.y - v.x) + fabsf(v.z - v.y)
             + fabsf(v.w - v.z) + fabsf(nx  - v.w);
    }

    #pragma unroll
    for (int off = 16; off > 0; off >>= 1)
        sum += __shfl_down_sync(0xFFFFFFFFu, sum, off);
    if (lane == 0)
        out[gwarp] = sum * inv;
}

// Generic fallback: one CTA per segment, scalar loads (any L >= 2).
__global__ __launch_bounds__(256) void seg_generic_kernel(
    const float* __restrict__ x,
    float* __restrict__ out,
    int L, float inv)
{
    const long long seg = blockIdx.x;
    const float* __restrict__ p = x + seg * (long long)L;
    const int tid = threadIdx.x;

    float sum = 0.0f;
    for (int i = tid; i < L - 1; i += blockDim.x)
        sum += fabsf(__ldg(p + i + 1) - __ldg(p + i));

    #pragma unroll
    for (int off = 16; off > 0; off >>= 1)
        sum += __shfl_down_sync(0xFFFFFFFFu, sum, off);

    __shared__ float wsum[8];
    const int lane = tid & 31, wid = tid >> 5;
    if (lane == 0) wsum[wid] = sum;
    __syncthreads();
    if (wid == 0) {
        float s = (lane < 8) ? wsum[lane] : 0.0f;
        #pragma unroll
        for (int off = 4; off > 0; off >>= 1)
            s += __shfl_down_sync(0xFFFFFFFFu, s, off);
        if (lane == 0) out[seg] = s * inv;
    }
}

extern "C" void kernel_launch(void* const* d_in, const int* in_sizes, int n_in,
                              void* d_out, int out_size)
{
    const float* x = (const float*)d_in[0];
    float* out = (float*)d_out;

    const long long total = (long long)in_sizes[0];
    const int num_segs = out_size;                     // B * target_len
    const int L = (int)(total / (long long)num_segs);  // segment length
    const float inv = 1.0f / (float)(L - 1);

    const int ctas = (num_segs * 32 + 255) / 256;

    if ((L % (BATCH * 128)) == 0 && L / (BATCH * 128) >= 2) {
        const int n4 = L >> 2;
        const int nbatches = n4 / (BATCH * 32);
        seg_warp_pipe_kernel<<<ctas, 256>>>(x, out, n4, nbatches, inv, num_segs);
    } else if ((L & 127) == 0) {
        const int n4 = L >> 2;
        seg_warp_kernel<<<ctas, 256>>>(x, out, n4, n4 >> 5, inv, num_segs);
    } else {
        seg_generic_kernel<<<num_segs, 256>>>(x, out, L, inv);
    }
}